// round 4
// baseline (speedup 1.0000x reference)
#include <cuda_runtime.h>
#include <cuda_bf16.h>
#include <cstdint>

#define T_DIM 8192
#define O_DIM 4096
#define I_DIM 4096
#define GROUPS 16   // I_DIM / 256

// ---- scratch (allocation-free rule: __device__ globals) ----
__device__ __nv_bfloat16 g_A[(size_t)T_DIM * I_DIM];   // 64 MB: (q - zp) per token, exact ints in bf16
__device__ __nv_bfloat16 g_B[(size_t)O_DIM * I_DIM];   // 32 MB: (w - zero) per group, exact ints in bf16
__device__ float        g_sx[T_DIM];                   // per-token scale

// ============================================================
// Kernel 1: per-token asymmetric int8 fake-quant -> a = q - zp (bf16)
// ============================================================
__global__ void quant_kernel(const float* __restrict__ x) {
    const int row = blockIdx.x;
    const int tid = threadIdx.x;
    const float4* xr = reinterpret_cast<const float4*>(x + (size_t)row * I_DIM);

    float4 v[4];
    float mn = 0.0f, mx = 0.0f;   // reference folds 0 into min/max
#pragma unroll
    for (int j = 0; j < 4; ++j) {
        v[j] = xr[tid + j * 256];
        mn = fminf(mn, fminf(fminf(v[j].x, v[j].y), fminf(v[j].z, v[j].w)));
        mx = fmaxf(mx, fmaxf(fmaxf(v[j].x, v[j].y), fmaxf(v[j].z, v[j].w)));
    }
    // warp reduce
#pragma unroll
    for (int o = 16; o > 0; o >>= 1) {
        mn = fminf(mn, __shfl_xor_sync(0xffffffffu, mn, o));
        mx = fmaxf(mx, __shfl_xor_sync(0xffffffffu, mx, o));
    }
    __shared__ float smn[8], smx[8];
    if ((tid & 31) == 0) { smn[tid >> 5] = mn; smx[tid >> 5] = mx; }
    __syncthreads();
    mn = smn[0]; mx = smx[0];
#pragma unroll
    for (int w = 1; w < 8; ++w) { mn = fminf(mn, smn[w]); mx = fmaxf(mx, smx[w]); }

    const float scale = fmaxf(__fdiv_rn(mx - mn, 255.0f), 1.1920929e-07f);
    const float dmin = __fdiv_rn(mn, scale);
    const float dmax = __fdiv_rn(mx, scale);
    float zp = ((-128.0f + dmin) + (127.0f + dmax) > 0.0f) ? (-128.0f - dmin)
                                                           : (127.0f - dmax);
    zp = rintf(fminf(fmaxf(zp, -128.0f), 127.0f));

    if (tid == 0) g_sx[row] = scale;

    __nv_bfloat16* Ar = g_A + (size_t)row * I_DIM;
#pragma unroll
    for (int j = 0; j < 4; ++j) {
        float e[4] = {v[j].x, v[j].y, v[j].z, v[j].w};
        __nv_bfloat16 bv[4];
#pragma unroll
        for (int c = 0; c < 4; ++c) {
            float q = rintf(__fdiv_rn(e[c], scale)) + zp;
            q = fminf(fmaxf(q, -128.0f), 127.0f);
            bv[c] = __float2bfloat16_rn(q - zp);  // integer in [-255,255]: exact
        }
        *reinterpret_cast<uint2*>(Ar + (size_t)(tid + j * 256) * 4) =
            *reinterpret_cast<uint2*>(bv);
    }
}

// ============================================================
// Kernel 2: weight prep  b = (w - zero[o,g])  (bf16, exact ints)
// ============================================================
__global__ void wprep_kernel(const int* __restrict__ w, const float* __restrict__ zeros) {
    const size_t e = ((size_t)blockIdx.x * 256 + threadIdx.x) * 4;
    const int4 wv = *reinterpret_cast<const int4*>(w + e);
    const int o = (int)(e >> 12);           // / I_DIM
    const int i = (int)(e & (I_DIM - 1));
    const int g = i >> 8;                   // / 256
    const float z = __ldg(&zeros[o * GROUPS + g]);
    __nv_bfloat16 bv[4];
    bv[0] = __float2bfloat16_rn((float)wv.x - z);
    bv[1] = __float2bfloat16_rn((float)wv.y - z);
    bv[2] = __float2bfloat16_rn((float)wv.z - z);
    bv[3] = __float2bfloat16_rn((float)wv.w - z);
    *reinterpret_cast<uint2*>(g_B + e) = *reinterpret_cast<uint2*>(bv);
}

// ============================================================
// Kernel 3: group-scaled bf16 GEMM (mma.sync), 128x128 tile, BK=32
// ============================================================
#define BK 32
#define LDS_STRIDE 40   // 32 + 8 pad: conflict-free, keeps 16B alignment (80B rows)
#define NKT (I_DIM / BK)  // 128 k-tiles; group boundary every 8

__device__ __forceinline__ void cp_async16(void* smem, const void* gmem) {
    unsigned s = (unsigned)__cvta_generic_to_shared(smem);
    asm volatile("cp.async.cg.shared.global [%0], [%1], 16;\n" :: "r"(s), "l"(gmem));
}
__device__ __forceinline__ void cp_commit() { asm volatile("cp.async.commit_group;\n"); }
__device__ __forceinline__ void cp_wait1()  { asm volatile("cp.async.wait_group 1;\n"); }
__device__ __forceinline__ void cp_wait0()  { asm volatile("cp.async.wait_group 0;\n"); }

__device__ __forceinline__ void load_kt(const __nv_bfloat16* Ag, const __nv_bfloat16* Bg,
                                        __nv_bfloat16* As, __nv_bfloat16* Bs,
                                        int k0, int ldrow, int ldcol) {
    cp_async16(As + ldrow * LDS_STRIDE + ldcol,        Ag + (size_t)ldrow * I_DIM + k0 + ldcol);
    cp_async16(As + (ldrow + 64) * LDS_STRIDE + ldcol, Ag + (size_t)(ldrow + 64) * I_DIM + k0 + ldcol);
    cp_async16(Bs + ldrow * LDS_STRIDE + ldcol,        Bg + (size_t)ldrow * I_DIM + k0 + ldcol);
    cp_async16(Bs + (ldrow + 64) * LDS_STRIDE + ldcol, Bg + (size_t)(ldrow + 64) * I_DIM + k0 + ldcol);
}

__global__ void __launch_bounds__(256, 1)
gemm_kernel(const float* __restrict__ scales, float* __restrict__ out) {
    __shared__ __align__(16) __nv_bfloat16 As[2][128 * LDS_STRIDE];
    __shared__ __align__(16) __nv_bfloat16 Bs[2][128 * LDS_STRIDE];

    const int tid  = threadIdx.x;
    const int bm   = blockIdx.y * 128;
    const int bn   = blockIdx.x * 128;
    const int lane = tid & 31, wid = tid >> 5;
    const int mbase = (wid >> 2) * 64;        // 2 warps in M
    const int nbase = (wid & 3) * 32;         // 4 warps in N
    const int r  = lane >> 2;                 // 0..7
    const int kq = (lane & 3) * 2;            // 0,2,4,6

    const int ldrow = tid >> 2;               // 0..63
    const int ldcol = (tid & 3) * 8;          // 0,8,16,24 (bf16 units = 16B chunks)

    const __nv_bfloat16* Ag = g_A + (size_t)bm * I_DIM;
    const __nv_bfloat16* Bg = g_B + (size_t)bn * I_DIM;

    float accg[4][4][4];   // per-group integer partials (exact)
    float acct[4][4][4];   // scaled totals
#pragma unroll
    for (int mi = 0; mi < 4; ++mi)
#pragma unroll
        for (int ni = 0; ni < 4; ++ni)
#pragma unroll
            for (int c = 0; c < 4; ++c) { accg[mi][ni][c] = 0.f; acct[mi][ni][c] = 0.f; }

    load_kt(Ag, Bg, As[0], Bs[0], 0, ldrow, ldcol);
    cp_commit();

    for (int kt = 0; kt < NKT; ++kt) {
        const int cur = kt & 1;
        if (kt + 1 < NKT) {
            load_kt(Ag, Bg, As[cur ^ 1], Bs[cur ^ 1], (kt + 1) * BK, ldrow, ldcol);
            cp_commit();
            cp_wait1();
        } else {
            cp_wait0();
        }
        __syncthreads();

#pragma unroll
        for (int k16 = 0; k16 < BK; k16 += 16) {
            unsigned a[4][4], b[4][2];
#pragma unroll
            for (int mi = 0; mi < 4; ++mi) {
                const __nv_bfloat16* p = &As[cur][(mbase + mi * 16 + r) * LDS_STRIDE + k16 + kq];
                a[mi][0] = *reinterpret_cast<const unsigned*>(p);
                a[mi][1] = *reinterpret_cast<const unsigned*>(p + 8 * LDS_STRIDE);
                a[mi][2] = *reinterpret_cast<const unsigned*>(p + 8);
                a[mi][3] = *reinterpret_cast<const unsigned*>(p + 8 * LDS_STRIDE + 8);
            }
#pragma unroll
            for (int ni = 0; ni < 4; ++ni) {
                const __nv_bfloat16* p = &Bs[cur][(nbase + ni * 8 + r) * LDS_STRIDE + k16 + kq];
                b[ni][0] = *reinterpret_cast<const unsigned*>(p);
                b[ni][1] = *reinterpret_cast<const unsigned*>(p + 8);
            }
#pragma unroll
            for (int mi = 0; mi < 4; ++mi)
#pragma unroll
                for (int ni = 0; ni < 4; ++ni) {
                    float* c = accg[mi][ni];
                    asm volatile(
                        "mma.sync.aligned.m16n8k16.row.col.f32.bf16.bf16.f32 "
                        "{%0,%1,%2,%3},{%4,%5,%6,%7},{%8,%9},{%0,%1,%2,%3};\n"
                        : "+f"(c[0]), "+f"(c[1]), "+f"(c[2]), "+f"(c[3])
                        : "r"(a[mi][0]), "r"(a[mi][1]), "r"(a[mi][2]), "r"(a[mi][3]),
                          "r"(b[ni][0]), "r"(b[ni][1]));
                }
        }

        // fold group scale every 256 K (8 tiles) — register-only
        if (((kt + 1) & 7) == 0) {
            const int g = kt >> 3;
#pragma unroll
            for (int ni = 0; ni < 4; ++ni) {
                const int col = bn + nbase + ni * 8 + kq;
                const float s0 = __ldg(&scales[col * GROUPS + g]);
                const float s1 = __ldg(&scales[(col + 1) * GROUPS + g]);
#pragma unroll
                for (int mi = 0; mi < 4; ++mi) {
                    acct[mi][ni][0] += s0 * accg[mi][ni][0];
                    acct[mi][ni][1] += s1 * accg[mi][ni][1];
                    acct[mi][ni][2] += s0 * accg[mi][ni][2];
                    acct[mi][ni][3] += s1 * accg[mi][ni][3];
                    accg[mi][ni][0] = 0.f; accg[mi][ni][1] = 0.f;
                    accg[mi][ni][2] = 0.f; accg[mi][ni][3] = 0.f;
                }
            }
        }
        __syncthreads();
    }

    // epilogue: out[t,o] = scale_x[t] * total
#pragma unroll
    for (int mi = 0; mi < 4; ++mi) {
        const int row0 = bm + mbase + mi * 16 + r;
        const int row1 = row0 + 8;
        const float sx0 = __ldg(&g_sx[row0]);
        const float sx1 = __ldg(&g_sx[row1]);
#pragma unroll
        for (int ni = 0; ni < 4; ++ni) {
            const int col = bn + nbase + ni * 8 + kq;
            float2 v0 = make_float2(sx0 * acct[mi][ni][0], sx0 * acct[mi][ni][1]);
            float2 v1 = make_float2(sx1 * acct[mi][ni][2], sx1 * acct[mi][ni][3]);
            *reinterpret_cast<float2*>(out + (size_t)row0 * O_DIM + col) = v0;
            *reinterpret_cast<float2*>(out + (size_t)row1 * O_DIM + col) = v1;
        }
    }
}

// ============================================================
extern "C" void kernel_launch(void* const* d_in, const int* in_sizes, int n_in,
                              void* d_out, int out_size) {
    const float* x      = (const float*)d_in[0];
    const int*   w      = (const int*)  d_in[1];
    const float* scales = (const float*)d_in[2];
    const float* zeros  = (const float*)d_in[3];
    float* out = (float*)d_out;

    quant_kernel<<<T_DIM, 256>>>(x);
    wprep_kernel<<<(O_DIM * (I_DIM / 4)) / 256, 256>>>(w, zeros);
    gemm_kernel<<<dim3(O_DIM / 128, T_DIM / 128), 256>>>(scales, out);
}

// round 6
// speedup vs baseline: 1.5685x; 1.5685x over previous
#include <cuda_runtime.h>
#include <cuda_bf16.h>
#include <cstdint>

#define T_DIM 8192
#define O_DIM 4096
#define I_DIM 4096
#define GROUPS 16   // I_DIM / 256

// ---- scratch (allocation-free rule: __device__ globals) ----
__device__ __nv_bfloat16 g_A[(size_t)T_DIM * I_DIM];   // 64 MB: (q - zp) per token, exact ints in bf16
__device__ __nv_bfloat16 g_B[(size_t)O_DIM * I_DIM];   // 32 MB: (w - zero) per group, exact ints in bf16
__device__ float        g_sx[T_DIM];                   // per-token scale

// ============================================================
// Kernel 1: per-token asymmetric int8 fake-quant -> a = q - zp (bf16)
// ============================================================
__global__ void quant_kernel(const float* __restrict__ x) {
    const int row = blockIdx.x;
    const int tid = threadIdx.x;
    const float4* xr = reinterpret_cast<const float4*>(x + (size_t)row * I_DIM);

    float4 v[4];
    float mn = 0.0f, mx = 0.0f;   // reference folds 0 into min/max
#pragma unroll
    for (int j = 0; j < 4; ++j) {
        v[j] = xr[tid + j * 256];
        mn = fminf(mn, fminf(fminf(v[j].x, v[j].y), fminf(v[j].z, v[j].w)));
        mx = fmaxf(mx, fmaxf(fmaxf(v[j].x, v[j].y), fmaxf(v[j].z, v[j].w)));
    }
#pragma unroll
    for (int o = 16; o > 0; o >>= 1) {
        mn = fminf(mn, __shfl_xor_sync(0xffffffffu, mn, o));
        mx = fmaxf(mx, __shfl_xor_sync(0xffffffffu, mx, o));
    }
    __shared__ float smn[8], smx[8];
    if ((tid & 31) == 0) { smn[tid >> 5] = mn; smx[tid >> 5] = mx; }
    __syncthreads();
    mn = smn[0]; mx = smx[0];
#pragma unroll
    for (int w = 1; w < 8; ++w) { mn = fminf(mn, smn[w]); mx = fmaxf(mx, smx[w]); }

    const float scale = fmaxf(__fdiv_rn(mx - mn, 255.0f), 1.1920929e-07f);
    const float dmin = __fdiv_rn(mn, scale);
    const float dmax = __fdiv_rn(mx, scale);
    float zp = ((-128.0f + dmin) + (127.0f + dmax) > 0.0f) ? (-128.0f - dmin)
                                                           : (127.0f - dmax);
    zp = rintf(fminf(fmaxf(zp, -128.0f), 127.0f));

    if (tid == 0) g_sx[row] = scale;

    __nv_bfloat16* Ar = g_A + (size_t)row * I_DIM;
#pragma unroll
    for (int j = 0; j < 4; ++j) {
        float e[4] = {v[j].x, v[j].y, v[j].z, v[j].w};
        __nv_bfloat16 bv[4];
#pragma unroll
        for (int c = 0; c < 4; ++c) {
            float q = rintf(__fdiv_rn(e[c], scale)) + zp;
            q = fminf(fmaxf(q, -128.0f), 127.0f);
            bv[c] = __float2bfloat16_rn(q - zp);  // integer in [-255,255]: exact
        }
        *reinterpret_cast<uint2*>(Ar + (size_t)(tid + j * 256) * 4) =
            *reinterpret_cast<uint2*>(bv);
    }
}

// ============================================================
// Kernel 2: weight prep  b = (w - zero[o,g])  (bf16, exact ints)
// ============================================================
__global__ void wprep_kernel(const int* __restrict__ w, const float* __restrict__ zeros) {
    const size_t e = ((size_t)blockIdx.x * 256 + threadIdx.x) * 4;
    const int4 wv = *reinterpret_cast<const int4*>(w + e);
    const int o = (int)(e >> 12);
    const int i = (int)(e & (I_DIM - 1));
    const int g = i >> 8;
    const float z = __ldg(&zeros[o * GROUPS + g]);
    __nv_bfloat16 bv[4];
    bv[0] = __float2bfloat16_rn((float)wv.x - z);
    bv[1] = __float2bfloat16_rn((float)wv.y - z);
    bv[2] = __float2bfloat16_rn((float)wv.z - z);
    bv[3] = __float2bfloat16_rn((float)wv.w - z);
    *reinterpret_cast<uint2*>(g_B + e) = *reinterpret_cast<uint2*>(bv);
}

// ============================================================
// Kernel 3: group-scaled bf16 GEMM (mma.sync + ldmatrix)
//   CTA 128x128, BK=64, 4-stage cp.async ring, 16 warps (32x32 each)
//   Per-group (K=256) integer partials in registers, folded by
//   scale[o,g]; scale_x[t] at the epilogue. All exact.
// ============================================================
#define BKB 128                 // bytes per smem row (64 bf16)
#define NSTG 4
#define STGB (128 * BKB)        // 16 KB per operand stage
#define NKB (I_DIM / 64)        // 64 k-blocks, 4 per group

__device__ __forceinline__ void cp_async16(uint32_t smem, const void* gmem) {
    asm volatile("cp.async.cg.shared.global [%0], [%1], 16;\n" :: "r"(smem), "l"(gmem));
}
__device__ __forceinline__ void cp_commit() { asm volatile("cp.async.commit_group;\n"); }
__device__ __forceinline__ void cp_wait2()  { asm volatile("cp.async.wait_group 2;\n"); }

__device__ __forceinline__ void ldmx4(unsigned& r0, unsigned& r1, unsigned& r2, unsigned& r3,
                                      uint32_t addr) {
    asm volatile("ldmatrix.sync.aligned.m8n8.x4.shared.b16 {%0,%1,%2,%3}, [%4];"
                 : "=r"(r0), "=r"(r1), "=r"(r2), "=r"(r3) : "r"(addr));
}

__global__ void __launch_bounds__(512, 1)
gemm_kernel(const float* __restrict__ scales, float* __restrict__ out) {
    extern __shared__ char smem_dyn[];
    uint32_t raw = (uint32_t)__cvta_generic_to_shared(smem_dyn);
    const uint32_t sA = (raw + 127u) & ~127u;            // 128B-aligned rows
    const uint32_t sB = sA + NSTG * STGB;
    float* s_sc = reinterpret_cast<float*>(smem_dyn + (sB + NSTG * STGB - raw));

    const int tid  = threadIdx.x;
    const int wid  = tid >> 5;
    const int lane = tid & 31;
    const int bm   = blockIdx.y * 128;
    const int bn   = blockIdx.x * 128;

    // warp grid 4(M) x 4(N); warp tile 32x32
    const int mbase = (wid & 3) * 32;
    const int nbase = (wid >> 2) * 32;
    const int q  = lane >> 3;          // ldmatrix address quad
    const int l7 = lane & 7;

    // --- producer indexing: each thread loads rows r0, r0+64, chunk j ---
    const int r0 = tid >> 3;           // 0..63
    const int j  = tid & 7;
    const uint32_t swoff = (uint32_t)((j ^ (r0 & 7)) << 4);
    const uint32_t dA0 = sA + r0 * BKB + swoff;
    const uint32_t dA1 = dA0 + 64 * BKB;          // (r0+64)&7 == r0&7
    const uint32_t dB0 = sB + r0 * BKB + swoff;
    const uint32_t dB1 = dB0 + 64 * BKB;
    const char* Ar0 = (const char*)(g_A + (size_t)(bm + r0) * I_DIM) + j * 16;
    const char* Ar1 = Ar0 + (size_t)64 * I_DIM * 2;
    const char* Br0 = (const char*)(g_B + (size_t)(bn + r0) * I_DIM) + j * 16;
    const char* Br1 = Br0 + (size_t)64 * I_DIM * 2;

    // --- ldmatrix per-lane row constants ---
    uint32_t arow128[2], arow7[2], brow128[2], brow7[2];
#pragma unroll
    for (int mi = 0; mi < 2; ++mi) {
        int r = mbase + mi * 16 + (q & 1) * 8 + l7;
        arow128[mi] = (uint32_t)(r * BKB);
        arow7[mi]   = (uint32_t)(r & 7);
    }
#pragma unroll
    for (int p = 0; p < 2; ++p) {
        int r = nbase + p * 16 + (q >> 1) * 8 + l7;
        brow128[p] = (uint32_t)(r * BKB);
        brow7[p]   = (uint32_t)(r & 7);
    }
    const uint32_t aq = (uint32_t)(q >> 1);   // A k-chunk offset
    const uint32_t bq = (uint32_t)(q & 1);    // B k-chunk offset

    // --- stage scales: s_sc[g*128 + col] = scales[(bn+col)*16 + g] ---
    for (int i = tid; i < GROUPS * 128; i += 512) {
        int g = i >> 7, c = i & 127;
        s_sc[i] = __ldg(&scales[(size_t)(bn + c) * GROUPS + g]);
    }

    float accg[2][4][4], acct[2][4][4];
#pragma unroll
    for (int mi = 0; mi < 2; ++mi)
#pragma unroll
        for (int ni = 0; ni < 4; ++ni)
#pragma unroll
            for (int c = 0; c < 4; ++c) { accg[mi][ni][c] = 0.f; acct[mi][ni][c] = 0.f; }

    // --- prologue: prefetch kb = 0,1,2 ---
#pragma unroll
    for (int kb = 0; kb < 3; ++kb) {
        const uint32_t so = (uint32_t)kb * STGB;
        const size_t go = (size_t)kb * BKB;
        cp_async16(dA0 + so, Ar0 + go);
        cp_async16(dA1 + so, Ar1 + go);
        cp_async16(dB0 + so, Br0 + go);
        cp_async16(dB1 + so, Br1 + go);
        cp_commit();
    }

    for (int kb = 0; kb < NKB; ++kb) {
        cp_wait2();
        __syncthreads();

        const uint32_t sAc = sA + (uint32_t)(kb & 3) * STGB;
        const uint32_t sBc = sB + (uint32_t)(kb & 3) * STGB;

#pragma unroll
        for (int k16 = 0; k16 < 4; ++k16) {
            unsigned a[2][4], b[4][2];
#pragma unroll
            for (int mi = 0; mi < 2; ++mi) {
                uint32_t addr = sAc + arow128[mi] + ((((uint32_t)(k16 << 1) + aq) ^ arow7[mi]) << 4);
                ldmx4(a[mi][0], a[mi][1], a[mi][2], a[mi][3], addr);
            }
#pragma unroll
            for (int p = 0; p < 2; ++p) {
                uint32_t addr = sBc + brow128[p] + ((((uint32_t)(k16 << 1) + bq) ^ brow7[p]) << 4);
                ldmx4(b[2 * p][0], b[2 * p][1], b[2 * p + 1][0], b[2 * p + 1][1], addr);
            }
#pragma unroll
            for (int mi = 0; mi < 2; ++mi)
#pragma unroll
                for (int ni = 0; ni < 4; ++ni) {
                    float* c = accg[mi][ni];
                    asm volatile(
                        "mma.sync.aligned.m16n8k16.row.col.f32.bf16.bf16.f32 "
                        "{%0,%1,%2,%3},{%4,%5,%6,%7},{%8,%9},{%0,%1,%2,%3};\n"
                        : "+f"(c[0]), "+f"(c[1]), "+f"(c[2]), "+f"(c[3])
                        : "r"(a[mi][0]), "r"(a[mi][1]), "r"(a[mi][2]), "r"(a[mi][3]),
                          "r"(b[ni][0]), "r"(b[ni][1]));
                }
        }

        // fold group scale every 256 K (4 kb) — register-only, exact
        if ((kb & 3) == 3) {
            const int g = kb >> 2;
            const float* sg = s_sc + g * 128;
#pragma unroll
            for (int ni = 0; ni < 4; ++ni) {
                const int c = nbase + ni * 8 + ((lane & 3) << 1);
                const float s0 = sg[c];
                const float s1 = sg[c + 1];
#pragma unroll
                for (int mi = 0; mi < 2; ++mi) {
                    acct[mi][ni][0] = fmaf(s0, accg[mi][ni][0], acct[mi][ni][0]);
                    acct[mi][ni][1] = fmaf(s1, accg[mi][ni][1], acct[mi][ni][1]);
                    acct[mi][ni][2] = fmaf(s0, accg[mi][ni][2], acct[mi][ni][2]);
                    acct[mi][ni][3] = fmaf(s1, accg[mi][ni][3], acct[mi][ni][3]);
                    accg[mi][ni][0] = 0.f; accg[mi][ni][1] = 0.f;
                    accg[mi][ni][2] = 0.f; accg[mi][ni][3] = 0.f;
                }
            }
        }

        // prefetch kb+3 into stage (kb+3)&3 (read last at kb-1; barrier above protects)
        if (kb + 3 < NKB) {
            const uint32_t so = (uint32_t)((kb + 3) & 3) * STGB;
            const size_t go = (size_t)(kb + 3) * BKB;
            cp_async16(dA0 + so, Ar0 + go);
            cp_async16(dA1 + so, Ar1 + go);
            cp_async16(dB0 + so, Br0 + go);
            cp_async16(dB1 + so, Br1 + go);
        }
        cp_commit();
    }

    // epilogue: out[t,o] = scale_x[t] * total
#pragma unroll
    for (int mi = 0; mi < 2; ++mi) {
        const int row0 = bm + mbase + mi * 16 + (lane >> 2);
        const int row1 = row0 + 8;
        const float sx0 = __ldg(&g_sx[row0]);
        const float sx1 = __ldg(&g_sx[row1]);
#pragma unroll
        for (int ni = 0; ni < 4; ++ni) {
            const int col = bn + nbase + ni * 8 + ((lane & 3) << 1);
            float2 v0 = make_float2(sx0 * acct[mi][ni][0], sx0 * acct[mi][ni][1]);
            float2 v1 = make_float2(sx1 * acct[mi][ni][2], sx1 * acct[mi][ni][3]);
            *reinterpret_cast<float2*>(out + (size_t)row0 * O_DIM + col) = v0;
            *reinterpret_cast<float2*>(out + (size_t)row1 * O_DIM + col) = v1;
        }
    }
}

#define SMEM_NEED (2 * NSTG * STGB + GROUPS * 128 * 4 + 256)

// ============================================================
extern "C" void kernel_launch(void* const* d_in, const int* in_sizes, int n_in,
                              void* d_out, int out_size) {
    const float* x      = (const float*)d_in[0];
    const int*   w      = (const int*)  d_in[1];
    const float* scales = (const float*)d_in[2];
    const float* zeros  = (const float*)d_in[3];
    float* out = (float*)d_out;

    cudaFuncSetAttribute(gemm_kernel, cudaFuncAttributeMaxDynamicSharedMemorySize, SMEM_NEED);

    quant_kernel<<<T_DIM, 256>>>(x);
    wprep_kernel<<<(O_DIM * (I_DIM / 4)) / 256, 256>>>(w, zeros);
    gemm_kernel<<<dim3(O_DIM / 128, T_DIM / 128), 512, SMEM_NEED>>>(scales, out);
}